// round 1
// baseline (speedup 1.0000x reference)
#include <cuda_runtime.h>

#define L_DIM 1024
#define OUT_DIM 512
#define M_TOT 16384  // B*N = 64*256

// Folded weight/bias scratch (no allocations allowed in kernel_launch).
__device__ float g_Wc[L_DIM * OUT_DIM];
__device__ float g_bc[OUT_DIM];

// Fold the three linears into one: Wc = 0.5*W_out + 0.5*W_in + W_root (alpha = 0.5)
__global__ void fold_weights_kernel(const float* __restrict__ W_in,
                                    const float* __restrict__ b_in,
                                    const float* __restrict__ W_out,
                                    const float* __restrict__ b_out,
                                    const float* __restrict__ W_root,
                                    const float* __restrict__ b_root) {
    int i = blockIdx.x * blockDim.x + threadIdx.x;
    if (i < L_DIM * OUT_DIM) {
        g_Wc[i] = 0.5f * W_out[i] + 0.5f * W_in[i] + W_root[i];
    }
    if (i < OUT_DIM) {
        g_bc[i] = 0.5f * b_out[i] + 0.5f * b_in[i] + b_root[i];
    }
}

// Tiled SGEMM: y[M_TOT, OUT_DIM] = x[M_TOT, L_DIM] @ g_Wc[L_DIM, OUT_DIM] + g_bc
// BM=128, BN=128, BK=16, 256 threads, each thread computes an 8x8 micro-tile.
#define BM 128
#define BN 128
#define BK 16
#define AS_STRIDE 132  // padded (multiple of 4 for float4-aligned reads, breaks worst bank conflicts)

__global__ __launch_bounds__(256, 2)
void gemm_bias_kernel(const float* __restrict__ x, float* __restrict__ y) {
    __shared__ float As[BK][AS_STRIDE];  // A stored transposed: As[k][m]
    __shared__ float Bs[BK][BN];         // B natural: Bs[k][n]

    const int bx = blockIdx.x;           // N tile index (0..3)
    const int by = blockIdx.y;           // M tile index (0..127)
    const int tid = threadIdx.x;
    const int tx = tid & 15;             // 0..15 -> N
    const int ty = tid >> 4;             // 0..15 -> M

    const float* A0 = x + (size_t)by * BM * L_DIM;
    const float* B0 = g_Wc + bx * BN;

    float acc[8][8];
#pragma unroll
    for (int i = 0; i < 8; i++)
#pragma unroll
        for (int j = 0; j < 8; j++) acc[i][j] = 0.0f;

    // A-load indexing: 128 rows x 16 cols = 512 float4; 2 per thread.
    const int a_r = tid >> 2;            // 0..63
    const int a_c = (tid & 3) << 2;      // 0,4,8,12
    // B-load indexing: 16 rows x 128 cols = 512 float4; 2 per thread.
    const int b_r = tid >> 5;            // 0..7
    const int b_c = (tid & 31) << 2;     // 0..124 step 4

    for (int k0 = 0; k0 < L_DIM; k0 += BK) {
        // Load A tile (transpose into As)
#pragma unroll
        for (int s = 0; s < 2; s++) {
            int r = a_r + s * 64;
            float4 v = *reinterpret_cast<const float4*>(A0 + (size_t)r * L_DIM + k0 + a_c);
            As[a_c + 0][r] = v.x;
            As[a_c + 1][r] = v.y;
            As[a_c + 2][r] = v.z;
            As[a_c + 3][r] = v.w;
        }
        // Load B tile
#pragma unroll
        for (int s = 0; s < 2; s++) {
            int r = b_r + s * 8;
            *reinterpret_cast<float4*>(&Bs[r][b_c]) =
                *reinterpret_cast<const float4*>(B0 + (size_t)(k0 + r) * OUT_DIM + b_c);
        }
        __syncthreads();

#pragma unroll
        for (int k = 0; k < BK; k++) {
            float a[8], b[8];
            // float4 reads (AS_STRIDE and BN are multiples of 4)
            *reinterpret_cast<float4*>(&a[0]) = *reinterpret_cast<const float4*>(&As[k][ty * 8 + 0]);
            *reinterpret_cast<float4*>(&a[4]) = *reinterpret_cast<const float4*>(&As[k][ty * 8 + 4]);
            *reinterpret_cast<float4*>(&b[0]) = *reinterpret_cast<const float4*>(&Bs[k][tx * 8 + 0]);
            *reinterpret_cast<float4*>(&b[4]) = *reinterpret_cast<const float4*>(&Bs[k][tx * 8 + 4]);
#pragma unroll
            for (int i = 0; i < 8; i++)
#pragma unroll
                for (int j = 0; j < 8; j++) acc[i][j] += a[i] * b[j];
        }
        __syncthreads();
    }

    // Epilogue: add bias, vectorized stores
    const int row0 = by * BM + ty * 8;
    const int col0 = bx * BN + tx * 8;
    float bb[8];
#pragma unroll
    for (int j = 0; j < 8; j++) bb[j] = g_bc[col0 + j];

#pragma unroll
    for (int i = 0; i < 8; i++) {
        float4 o0, o1;
        o0.x = acc[i][0] + bb[0];
        o0.y = acc[i][1] + bb[1];
        o0.z = acc[i][2] + bb[2];
        o0.w = acc[i][3] + bb[3];
        o1.x = acc[i][4] + bb[4];
        o1.y = acc[i][5] + bb[5];
        o1.z = acc[i][6] + bb[6];
        o1.w = acc[i][7] + bb[7];
        float* yrow = y + (size_t)(row0 + i) * OUT_DIM + col0;
        *reinterpret_cast<float4*>(yrow + 0) = o0;
        *reinterpret_cast<float4*>(yrow + 4) = o1;
    }
}

extern "C" void kernel_launch(void* const* d_in, const int* in_sizes, int n_in,
                              void* d_out, int out_size) {
    // metadata order: x, At, W_in, b_in, W_out, b_out, W_root, b_root
    const float* x      = (const float*)d_in[0];
    // d_in[1] = At (int32) — mathematically dead in the reference (ChebConv K=1)
    const float* W_in   = (const float*)d_in[2];
    const float* b_in   = (const float*)d_in[3];
    const float* W_out  = (const float*)d_in[4];
    const float* b_out  = (const float*)d_in[5];
    const float* W_root = (const float*)d_in[6];
    const float* b_root = (const float*)d_in[7];
    float* y = (float*)d_out;

    fold_weights_kernel<<<(L_DIM * OUT_DIM + 255) / 256, 256>>>(
        W_in, b_in, W_out, b_out, W_root, b_root);

    dim3 grid(OUT_DIM / BN, M_TOT / BM);  // (4, 128)
    gemm_bias_kernel<<<grid, 256>>>(x, y);
}

// round 3
// speedup vs baseline: 2.6444x; 2.6444x over previous
#include <cuda_runtime.h>
#include <cuda_bf16.h>
#include <cstdint>

#define L_DIM   1024
#define OUT_DIM 512
#define M_TOT   16384       // B*N = 64*256
#define BM      128
#define BN      256
#define KC      32
#define NCHUNK  (L_DIM / KC)   // 32
#define THREADS 256

// ---------------- device scratch (no allocations allowed) ----------------
__device__ __align__(128) unsigned short g_w_hi[L_DIM * OUT_DIM];  // bf16 bits, [K,N]
__device__ __align__(128) unsigned short g_w_lo[L_DIM * OUT_DIM];  // bf16 bits, [K,N]
__device__ float g_bc[OUT_DIM];

// ---------------- smem layout (dynamic) ----------------
// bias:   [0, 1024)
// A tiles: row stride 80B (32 bf16 = 64B + 16B pad), tile = 128*80 = 10240B
//   Ah(s) = 1024 + s*20480 ; Al(s) = Ah(s) + 10240
// B tiles: row stride 528B (256 bf16 = 512B + 16B pad), tile = 32*528 = 16896B
//   Bh(s) = 41984 + s*33792 ; Bl(s) = Bh(s) + 16896
#define SM_BIAS   0
#define SM_A      1024
#define A_RSTRIDE 80
#define A_TILE    (BM * A_RSTRIDE)
#define SM_B      (SM_A + 4 * A_TILE)
#define B_RSTRIDE 528
#define B_TILE    (KC * B_RSTRIDE)
#define SMEM_NEED (SM_B + 4 * B_TILE)   // 109568 bytes

__device__ __forceinline__ uint32_t smem_to_u32(const void* p) {
    uint32_t a;
    asm("{ .reg .u64 t; cvta.to.shared.u64 t, %1; cvt.u32.u64 %0, t; }" : "=r"(a) : "l"(p));
    return a;
}

#define CP_ASYNC16(dst, src) \
    asm volatile("cp.async.cg.shared.global [%0], [%1], 16;" :: "r"(dst), "l"(src) : "memory")
#define CP_COMMIT()  asm volatile("cp.async.commit_group;" ::: "memory")
#define CP_WAIT_ALL() asm volatile("cp.async.wait_group 0;" ::: "memory")

#define LDMATRIX_X4(r0, r1, r2, r3, addr) \
    asm volatile("ldmatrix.sync.aligned.m8n8.x4.shared.b16 {%0,%1,%2,%3}, [%4];" \
        : "=r"(r0), "=r"(r1), "=r"(r2), "=r"(r3) : "r"(addr))
#define LDMATRIX_X4_T(r0, r1, r2, r3, addr) \
    asm volatile("ldmatrix.sync.aligned.m8n8.x4.trans.shared.b16 {%0,%1,%2,%3}, [%4];" \
        : "=r"(r0), "=r"(r1), "=r"(r2), "=r"(r3) : "r"(addr))

#define MMA_BF16(d, a, b) \
    asm volatile("mma.sync.aligned.m16n8k16.row.col.f32.bf16.bf16.f32 " \
        "{%0,%1,%2,%3}, {%4,%5,%6,%7}, {%8,%9}, {%0,%1,%2,%3};" \
        : "+f"((d)[0]), "+f"((d)[1]), "+f"((d)[2]), "+f"((d)[3]) \
        : "r"((a)[0]), "r"((a)[1]), "r"((a)[2]), "r"((a)[3]), "r"((b)[0]), "r"((b)[1]))

// split fp32 pair into hi bf16x2 (exact round) + lo bf16x2 (residual)
__device__ __forceinline__ void split2(float f0, float f1, uint32_t& h, uint32_t& l) {
    asm("cvt.rn.bf16x2.f32 %0, %1, %2;" : "=r"(h) : "f"(f1), "f"(f0));  // hi<-f1, lo<-f0
    float h0 = __uint_as_float(h << 16);
    float h1 = __uint_as_float(h & 0xFFFF0000u);
    float l0 = f0 - h0;
    float l1 = f1 - h1;
    asm("cvt.rn.bf16x2.f32 %0, %1, %2;" : "=r"(l) : "f"(l1), "f"(l0));
}

// ---------------- prep: fold 3 linears (same [K,N] layout), split bf16 ----
__global__ void prep_weights(const float* __restrict__ W_in, const float* __restrict__ b_in,
                             const float* __restrict__ W_out, const float* __restrict__ b_out,
                             const float* __restrict__ W_root, const float* __restrict__ b_root) {
    int i = blockIdx.x * blockDim.x + threadIdx.x;
    if (i < L_DIM * OUT_DIM) {
        float wc = 0.5f * W_out[i] + 0.5f * W_in[i] + W_root[i];
        __nv_bfloat16 hi = __float2bfloat16_rn(wc);
        float lo_f = wc - __bfloat162float(hi);
        g_w_hi[i] = __bfloat16_as_ushort(hi);
        g_w_lo[i] = __bfloat16_as_ushort(__float2bfloat16_rn(lo_f));
    }
    if (i < OUT_DIM) {
        g_bc[i] = 0.5f * b_out[i] + 0.5f * b_in[i] + b_root[i];
    }
}

// ---------------- GEMM: 128x256 CTA tile, mma.sync bf16 3-term split ------
__global__ __launch_bounds__(THREADS, 1)
void gemm_hmma(const float* __restrict__ x, float* __restrict__ y) {
    extern __shared__ char smem[];
    const uint32_t sb = smem_to_u32(smem);
    float* sbias = (float*)smem;

    const int tid  = threadIdx.x;
    const int wid  = tid >> 5;
    const int lane = tid & 31;
    const int m0 = blockIdx.y * BM;
    const int n0 = blockIdx.x * BN;
    const int m_warp = (wid >> 2) * 64;     // 0 or 64
    const int n_warp = (wid & 3) * 64;      // 0,64,128,192

    sbias[tid] = g_bc[n0 + tid];

    float acc[4][8][4];
#pragma unroll
    for (int i = 0; i < 4; i++)
#pragma unroll
        for (int j = 0; j < 8; j++)
#pragma unroll
            for (int q = 0; q < 4; q++) acc[i][j][q] = 0.0f;

    // ---- per-thread load indices ----
    // B cp.async: 1024 16B-chunks per (hi|lo) tile -> 4 per thread each
    const int b_row  = tid >> 3;                 // reuse pattern below per j
    (void)b_row;
    // A ldg: 1024 float4 per chunk -> 4 per thread
    const int a_row0 = tid >> 3;                 // 0..31 (+32 per j)
    const int a_cb   = tid & 7;                  // float4 column block (0..7)

    const char* whp = (const char*)g_w_hi;
    const char* wlp = (const char*)g_w_lo;

    auto cp_b_tile = [&](int chunk, int stage) {
        const uint32_t bh = sb + SM_B + stage * 2 * B_TILE;
        const uint32_t bl = bh + B_TILE;
        const size_t kbase = (size_t)chunk * KC;
#pragma unroll
        for (int j = 0; j < 4; j++) {
            int idx = tid + j * 256;             // 0..1023
            int r   = idx >> 5;                  // k row 0..31
            int cb  = (idx & 31) * 16;           // byte within 512B row
            size_t srcoff = ((kbase + r) * OUT_DIM + n0) * 2 + cb;
            uint32_t dsw = (uint32_t)(r * B_RSTRIDE + cb);
            CP_ASYNC16(bh + dsw, whp + srcoff);
            CP_ASYNC16(bl + dsw, wlp + srcoff);
        }
    };

    // ---- prologue ----
    cp_b_tile(0, 0);
    CP_COMMIT();

    float4 av[4];
    {
        const float* src = x + (size_t)m0 * L_DIM;  // chunk 0
#pragma unroll
        for (int j = 0; j < 4; j++)
            av[j] = *(const float4*)(src + (size_t)(a_row0 + j * 32) * L_DIM + a_cb * 4);
    }
    // split + STS chunk0 into stage0
    {
        const uint32_t ah = sb + SM_A;
        const uint32_t al = ah + A_TILE;
#pragma unroll
        for (int j = 0; j < 4; j++) {
            int r = a_row0 + j * 32;
            uint32_t h0, h1, l0, l1;
            split2(av[j].x, av[j].y, h0, l0);
            split2(av[j].z, av[j].w, h1, l1);
            uint32_t off = (uint32_t)(r * A_RSTRIDE + a_cb * 8);
            asm volatile("st.shared.v2.b32 [%0], {%1,%2};" :: "r"(ah + off), "r"(h0), "r"(h1) : "memory");
            asm volatile("st.shared.v2.b32 [%0], {%1,%2};" :: "r"(al + off), "r"(l0), "r"(l1) : "memory");
        }
    }
    // prefetch chunk 1 into regs
    {
        const float* src = x + (size_t)m0 * L_DIM + KC;
#pragma unroll
        for (int j = 0; j < 4; j++)
            av[j] = *(const float4*)(src + (size_t)(a_row0 + j * 32) * L_DIM + a_cb * 4);
    }
    CP_WAIT_ALL();
    __syncthreads();

    // ---- main loop ----
#pragma unroll 2
    for (int i = 0; i < NCHUNK; i++) {
        const int s = i & 1;
        const int o = s ^ 1;

        if (i + 1 < NCHUNK) {
            cp_b_tile(i + 1, o);
            CP_COMMIT();
            // split av (= chunk i+1) into A stage o
            const uint32_t ah = sb + SM_A + o * 2 * A_TILE;
            const uint32_t al = ah + A_TILE;
#pragma unroll
            for (int j = 0; j < 4; j++) {
                int r = a_row0 + j * 32;
                uint32_t h0, h1, l0, l1;
                split2(av[j].x, av[j].y, h0, l0);
                split2(av[j].z, av[j].w, h1, l1);
                uint32_t off = (uint32_t)(r * A_RSTRIDE + a_cb * 8);
                asm volatile("st.shared.v2.b32 [%0], {%1,%2};" :: "r"(ah + off), "r"(h0), "r"(h1) : "memory");
                asm volatile("st.shared.v2.b32 [%0], {%1,%2};" :: "r"(al + off), "r"(l0), "r"(l1) : "memory");
            }
        }
        if (i + 2 < NCHUNK) {
            const float* src = x + (size_t)m0 * L_DIM + (size_t)(i + 2) * KC;
#pragma unroll
            for (int j = 0; j < 4; j++)
                av[j] = *(const float4*)(src + (size_t)(a_row0 + j * 32) * L_DIM + a_cb * 4);
        }

        // ---- MMA on stage s ----
        const uint32_t ah = sb + SM_A + s * 2 * A_TILE;
        const uint32_t al = ah + A_TILE;
        const uint32_t bh = sb + SM_B + s * 2 * B_TILE;
        const uint32_t bl = bh + B_TILE;
#pragma unroll
        for (int ks = 0; ks < 2; ks++) {
            uint32_t bfh[8][2], bfl[8][2], af[4][4];
            // B frags (x4.trans loads 2 n-frags at once)
#pragma unroll
            for (int p = 0; p < 4; p++) {
                uint32_t roff = (uint32_t)((ks * 16 + (lane & 15)) * B_RSTRIDE
                                           + (n_warp + p * 16 + ((lane >> 4) << 3)) * 2);
                LDMATRIX_X4_T(bfh[p * 2][0], bfh[p * 2][1], bfh[p * 2 + 1][0], bfh[p * 2 + 1][1], bh + roff);
                LDMATRIX_X4_T(bfl[p * 2][0], bfl[p * 2][1], bfl[p * 2 + 1][0], bfl[p * 2 + 1][1], bl + roff);
            }
            // A_hi frags
#pragma unroll
            for (int mi = 0; mi < 4; mi++) {
                uint32_t roff = (uint32_t)((m_warp + mi * 16 + (lane & 15)) * A_RSTRIDE
                                           + ((lane >> 4) << 4) + ks * 32);
                LDMATRIX_X4(af[mi][0], af[mi][1], af[mi][2], af[mi][3], ah + roff);
            }
#pragma unroll
            for (int mi = 0; mi < 4; mi++)
#pragma unroll
                for (int nj = 0; nj < 8; nj++) {
                    MMA_BF16(acc[mi][nj], af[mi], bfh[nj]);
                    MMA_BF16(acc[mi][nj], af[mi], bfl[nj]);
                }
            // A_lo frags (reuse af regs)
#pragma unroll
            for (int mi = 0; mi < 4; mi++) {
                uint32_t roff = (uint32_t)((m_warp + mi * 16 + (lane & 15)) * A_RSTRIDE
                                           + ((lane >> 4) << 4) + ks * 32);
                LDMATRIX_X4(af[mi][0], af[mi][1], af[mi][2], af[mi][3], al + roff);
            }
#pragma unroll
            for (int mi = 0; mi < 4; mi++)
#pragma unroll
                for (int nj = 0; nj < 8; nj++)
                    MMA_BF16(acc[mi][nj], af[mi], bfh[nj]);
        }

        CP_WAIT_ALL();
        __syncthreads();
    }

    // ---- epilogue: bias add + store ----
#pragma unroll
    for (int mi = 0; mi < 4; mi++) {
        int r0 = m0 + m_warp + mi * 16 + (lane >> 2);
#pragma unroll
        for (int nj = 0; nj < 8; nj++) {
            int cl = n_warp + nj * 8 + (lane & 3) * 2;
            float b0 = sbias[cl], b1 = sbias[cl + 1];
            float2 v0 = make_float2(acc[mi][nj][0] + b0, acc[mi][nj][1] + b1);
            float2 v1 = make_float2(acc[mi][nj][2] + b0, acc[mi][nj][3] + b1);
            *(float2*)(y + (size_t)r0 * OUT_DIM + n0 + cl) = v0;
            *(float2*)(y + (size_t)(r0 + 8) * OUT_DIM + n0 + cl) = v1;
        }
    }
}

// ---------------- launch ----------------
extern "C" void kernel_launch(void* const* d_in, const int* in_sizes, int n_in,
                              void* d_out, int out_size) {
    // metadata order: x, At, W_in, b_in, W_out, b_out, W_root, b_root
    const float* x      = (const float*)d_in[0];
    // d_in[1] = At — mathematically dead (ChebConv K=1: no neighbor aggregation)
    const float* W_in   = (const float*)d_in[2];
    const float* b_in   = (const float*)d_in[3];
    const float* W_out  = (const float*)d_in[4];
    const float* b_out  = (const float*)d_in[5];
    const float* W_root = (const float*)d_in[6];
    const float* b_root = (const float*)d_in[7];
    float* y = (float*)d_out;

    prep_weights<<<(L_DIM * OUT_DIM + 255) / 256, 256>>>(W_in, b_in, W_out, b_out, W_root, b_root);

    cudaFuncSetAttribute(gemm_hmma, cudaFuncAttributeMaxDynamicSharedMemorySize, SMEM_NEED);
    gemm_hmma<<<dim3(OUT_DIM / BN, M_TOT / BM), THREADS, SMEM_NEED>>>(x, y);
}